// round 2
// baseline (speedup 1.0000x reference)
#include <cuda_runtime.h>
#include <math.h>

// Problem constants (fixed shapes for this problem)
#define B_  16
#define N_  2048
#define E_  1024
#define G_  2
#define V_  320
#define D_  512
#define GV_ 640            // G*V
#define M_  (B_ * N_)      // 32768 rows of the GEMM
#define ROWS_ (M_ * G_)    // 65536 (b,n,g) rows for argmax

// Scratch: logits h [M_, GV_] = 84 MB, and per-(b,g) histograms.
__device__ float g_h[(size_t)M_ * GV_];
__device__ int   g_counts[B_ * G_ * V_];

// ---------------------------------------------------------------------------
// Kernel 0: zero the histograms (graph-replay safe; no memset API needed)
// ---------------------------------------------------------------------------
__global__ void zero_counts_kernel() {
    int i = blockIdx.x * blockDim.x + threadIdx.x;
    if (i < B_ * G_ * V_) g_counts[i] = 0;
}

// ---------------------------------------------------------------------------
// Kernel 1: fp32 SGEMM  h = x @ W   (bias added later in kernel 2)
// x: [32768, 1024] row-major, W: [1024, 640] row-major, h: [32768, 640]
// BM=128, BN=128, BK=8, 256 threads, 8x8 micro-tile in split layout
// (rows {ty*4..+3, 64+ty*4..+3} x cols {tx*4..+3, 64+tx*4..+3}) so all
// LDS are float4 broadcast/stride-4 conflict-free. Register-prefetch of the
// next k-tile's global loads hides LDG latency behind the FMA block.
// ---------------------------------------------------------------------------
__global__ __launch_bounds__(256, 2)
void sgemm_kernel(const float* __restrict__ A, const float* __restrict__ W) {
    const int K = E_;      // 1024
    const int N = GV_;     // 640

    __shared__ float As[8][132];   // [k][m], padded
    __shared__ float Bs[8][128];   // [k][n]

    const int tid  = threadIdx.x;
    const int bm   = blockIdx.y * 128;
    const int bn   = blockIdx.x * 128;

    const int arow = tid >> 1;            // 0..127
    const int acol = (tid & 1) << 2;      // 0 or 4
    const int brow = tid >> 5;            // 0..7
    const int bcol = (tid & 31) << 2;     // 0..124

    const int tx = tid & 15;              // column group
    const int ty = tid >> 4;              // row group (0..15)

    float acc[8][8];
#pragma unroll
    for (int i = 0; i < 8; i++)
#pragma unroll
        for (int j = 0; j < 8; j++) acc[i][j] = 0.0f;

    const float* Ap = A + (size_t)(bm + arow) * K + acol;
    const float* Wp = W + (size_t)brow * N + bn + bcol;

    // Prefetch first k-tile
    float4 av = *(const float4*)(Ap);
    float4 bv = *(const float4*)(Wp);

    for (int k0 = 0; k0 < K; k0 += 8) {
        As[acol + 0][arow] = av.x;
        As[acol + 1][arow] = av.y;
        As[acol + 2][arow] = av.z;
        As[acol + 3][arow] = av.w;
        *(float4*)&Bs[brow][bcol] = bv;
        __syncthreads();

        // Issue next tile's global loads before the FMA block (latency hiding)
        if (k0 + 8 < K) {
            av = *(const float4*)(Ap + k0 + 8);
            bv = *(const float4*)(Wp + (size_t)(k0 + 8) * N);
        }

#pragma unroll
        for (int kk = 0; kk < 8; kk++) {
            float a0[4], a1[4], b0[4], b1[4];
            *(float4*)a0 = *(const float4*)&As[kk][ty * 4];
            *(float4*)a1 = *(const float4*)&As[kk][64 + ty * 4];
            *(float4*)b0 = *(const float4*)&Bs[kk][tx * 4];
            *(float4*)b1 = *(const float4*)&Bs[kk][64 + tx * 4];
#pragma unroll
            for (int i = 0; i < 4; i++) {
#pragma unroll
                for (int j = 0; j < 4; j++) {
                    acc[i][j]         = fmaf(a0[i], b0[j], acc[i][j]);
                    acc[i][j + 4]     = fmaf(a0[i], b1[j], acc[i][j + 4]);
                    acc[i + 4][j]     = fmaf(a1[i], b0[j], acc[i + 4][j]);
                    acc[i + 4][j + 4] = fmaf(a1[i], b1[j], acc[i + 4][j + 4]);
                }
            }
        }
        __syncthreads();
    }

    // Writeback to g_h
#pragma unroll
    for (int hr = 0; hr < 2; hr++) {
#pragma unroll
        for (int i = 0; i < 4; i++) {
            int row = bm + hr * 64 + ty * 4 + i;
            float* cp = g_h + (size_t)row * N + bn;
            float4 v0, v1;
            v0.x = acc[hr * 4 + i][0]; v0.y = acc[hr * 4 + i][1];
            v0.z = acc[hr * 4 + i][2]; v0.w = acc[hr * 4 + i][3];
            v1.x = acc[hr * 4 + i][4]; v1.y = acc[hr * 4 + i][5];
            v1.z = acc[hr * 4 + i][6]; v1.w = acc[hr * 4 + i][7];
            *(float4*)(cp + tx * 4)      = v0;
            *(float4*)(cp + 64 + tx * 4) = v1;
        }
    }
}

// ---------------------------------------------------------------------------
// Kernel 2: per-(b,n,g) row: gumbel + bias + argmax over V=320,
// histogram atomic, and gather the selected codebook vector into out.
// One warp per row. h and u share the same linear layout: offset = r*V_.
// ---------------------------------------------------------------------------
__global__ __launch_bounds__(256)
void argmax_gather_kernel(const float* __restrict__ u,
                          const float* __restrict__ bias,
                          const float* __restrict__ codebook,
                          float* __restrict__ out) {
    const int warp = (blockIdx.x * blockDim.x + threadIdx.x) >> 5;
    const int lane = threadIdx.x & 31;
    if (warp >= ROWS_) return;

    const int r    = warp;                 // ((b*N + n)*G + g)
    const int gidx = r & 1;                // G_ == 2
    const float* hrow = g_h + (size_t)r * V_;
    const float* urow = u   + (size_t)r * V_;
    const float* brow = bias + gidx * V_;

    // u*(1-2e)+e with eps=1e-7, matching the reference's fp32 arithmetic
    const float kA = 1.0f - 2.0f * 1e-7f;
    const float kB = 1e-7f;

    float best = -3.4e38f;
    int   bi   = 0;
    for (int v = lane; v < V_; v += 32) {
        float uu = fmaf(urow[v], kA, kB);
        float gn = -logf(-logf(uu));
        float val = hrow[v] + brow[v] + gn;
        if (val > best) { best = val; bi = v; }   // strict >: keeps first index
    }
    // warp argmax reduce, first-index tie-break
#pragma unroll
    for (int off = 16; off; off >>= 1) {
        float ov = __shfl_down_sync(0xffffffffu, best, off);
        int   oi = __shfl_down_sync(0xffffffffu, bi,   off);
        if (ov > best || (ov == best && oi < bi)) { best = ov; bi = oi; }
    }
    bi = __shfl_sync(0xffffffffu, bi, 0);

    if (lane == 0) {
        int b = r >> 12;                  // r / (N_*G_)
        atomicAdd(&g_counts[(b * G_ + gidx) * V_ + bi], 1);
    }

    // Gather codebook[g, bi, :] -> out[r*D_ .. r*D_+511]
    const float4* cb = (const float4*)(codebook + ((size_t)(gidx * V_ + bi)) * D_);
    float4*       op = (float4*)(out + (size_t)r * D_);
#pragma unroll
    for (int i = 0; i < 4; i++) {
        op[i * 32 + lane] = cb[i * 32 + lane];
    }
}

// ---------------------------------------------------------------------------
// Kernel 3: entropy from histograms. 32 warps, one per (b,g).
// entropy = -sum_{b,g,v} p*log(p+1e-8) / (G*V), p = softmax(counts, axis=V)
// ---------------------------------------------------------------------------
__global__ void entropy_kernel(float* __restrict__ out, int out_size) {
    const int w    = threadIdx.x >> 5;     // 0..31 == (b*G+g)
    const int lane = threadIdx.x & 31;
    const int* c = g_counts + w * V_;

    float cv[10];
    float m = -3.4e38f;
#pragma unroll
    for (int i = 0; i < 10; i++) {
        cv[i] = (float)c[lane + i * 32];
        m = fmaxf(m, cv[i]);
    }
#pragma unroll
    for (int off = 16; off; off >>= 1)
        m = fmaxf(m, __shfl_xor_sync(0xffffffffu, m, off));

    float s = 0.0f;
#pragma unroll
    for (int i = 0; i < 10; i++) s += expf(cv[i] - m);
#pragma unroll
    for (int off = 16; off; off >>= 1)
        s += __shfl_xor_sync(0xffffffffu, s, off);

    float ent = 0.0f;
#pragma unroll
    for (int i = 0; i < 10; i++) {
        float p = expf(cv[i] - m) / s;
        ent += p * logf(p + 1e-8f);
    }
#pragma unroll
    for (int off = 16; off; off >>= 1)
        ent += __shfl_xor_sync(0xffffffffu, ent, off);

    __shared__ float part[32];
    if (lane == 0) part[w] = ent;
    __syncthreads();
    if (threadIdx.x == 0) {
        float t = 0.0f;
#pragma unroll
        for (int i = 0; i < 32; i++) t += part[i];
        out[out_size - 1] = -t / (float)(G_ * V_);
    }
}

// ---------------------------------------------------------------------------
extern "C" void kernel_launch(void* const* d_in, const int* in_sizes, int n_in,
                              void* d_out, int out_size) {
    const float* x        = (const float*)d_in[0];  // [16,2048,1024]
    const float* u        = (const float*)d_in[1];  // [16,2048,2,320]
    const float* W        = (const float*)d_in[2];  // [1024,640]
    const float* bias     = (const float*)d_in[3];  // [640]
    const float* codebook = (const float*)d_in[4];  // [2,320,512]
    float* out = (float*)d_out;

    (void)in_sizes; (void)n_in;

    zero_counts_kernel<<<(B_ * G_ * V_ + 255) / 256, 256>>>();

    dim3 gg(GV_ / 128, M_ / 128);   // (5, 256)
    sgemm_kernel<<<gg, 256>>>(x, W);

    argmax_gather_kernel<<<(ROWS_ * 32 + 255) / 256, 256>>>(u, bias, codebook, out);

    entropy_kernel<<<1, 1024>>>(out, out_size);
}

// round 5
// speedup vs baseline: 3.2948x; 3.2948x over previous
#include <cuda_runtime.h>
#include <cuda_bf16.h>
#include <math.h>

// Problem constants
#define B_  16
#define N_  2048
#define E_  1024
#define G_  2
#define V_  320
#define D_  512
#define GV_ 640
#define M_  (B_ * N_)
#define ROWS_ (M_ * G_)

#define BK   32
#define NIT  (E_ / BK)
#define APITCH 40
#define THRESH 0.05f

// smem layout constants (bytes)
#define STG_BYTES  10240   /* 128 * APITCH * 2 */
#define HALF_BYTES 5120    /* 64 * APITCH * 2  */

// Device scratch (sanctioned: __device__ globals, no allocation)
__device__ __nv_bfloat16 g_xb[(size_t)M_ * E_];
__device__ __nv_bfloat16 g_wt[(size_t)GV_ * E_];
__device__ float         g_h[(size_t)M_ * GV_];
__device__ int           g_counts[B_ * G_ * V_];

// ---------------------------------------------------------------------------
// PTX helpers (plain inline functions, no function-like macros)
// ---------------------------------------------------------------------------
__device__ __forceinline__ unsigned smem_u32(const void* p) {
    unsigned a;
    asm("{ .reg .u64 t; cvta.to.shared.u64 t, %1; cvt.u32.u64 %0, t; }"
        : "=r"(a) : "l"(p));
    return a;
}

__device__ __forceinline__ void cp_async16(unsigned dst, const void* src) {
    asm volatile("cp.async.cg.shared.global [%0], [%1], 16;" :: "r"(dst), "l"(src));
}

__device__ __forceinline__ void cp_commit() {
    asm volatile("cp.async.commit_group;" ::: "memory");
}

__device__ __forceinline__ void cp_wait0() {
    asm volatile("cp.async.wait_group 0;" ::: "memory");
}

__device__ __forceinline__ void cp_wait1() {
    asm volatile("cp.async.wait_group 1;" ::: "memory");
}

__device__ __forceinline__ void ldsm4(unsigned* r, unsigned addr) {
    asm volatile("ldmatrix.sync.aligned.m8n8.x4.shared.b16 {%0,%1,%2,%3}, [%4];"
                 : "=r"(r[0]), "=r"(r[1]), "=r"(r[2]), "=r"(r[3]) : "r"(addr));
}

__device__ __forceinline__ void mma16816(float* c, const unsigned* a,
                                         unsigned b0, unsigned b1) {
    asm volatile(
        "mma.sync.aligned.m16n8k16.row.col.f32.bf16.bf16.f32 "
        "{%0,%1,%2,%3}, {%4,%5,%6,%7}, {%8,%9}, {%0,%1,%2,%3};"
        : "+f"(c[0]), "+f"(c[1]), "+f"(c[2]), "+f"(c[3])
        : "r"(a[0]), "r"(a[1]), "r"(a[2]), "r"(a[3]), "r"(b0), "r"(b1));
}

// Issue one k-tile of cp.async loads for both A and B (4 x 16B per thread).
__device__ __forceinline__ void issue_tile(unsigned dA, unsigned dB,
                                           const __nv_bfloat16* ag,
                                           const __nv_bfloat16* bg) {
    cp_async16(dA,              ag);
    cp_async16(dA + HALF_BYTES, ag + (size_t)64 * E_);
    cp_async16(dB,              bg);
    cp_async16(dB + HALF_BYTES, bg + (size_t)64 * E_);
    cp_commit();
}

// ---------------------------------------------------------------------------
// Kernel 0: zero histograms
// ---------------------------------------------------------------------------
__global__ void zero_counts_kernel() {
    int i = blockIdx.x * blockDim.x + threadIdx.x;
    if (i < B_ * G_ * V_) g_counts[i] = 0;
}

// ---------------------------------------------------------------------------
// Kernel 1a: convert x (f32) -> g_xb (bf16)
// ---------------------------------------------------------------------------
__global__ __launch_bounds__(256)
void convert_x_kernel(const float* __restrict__ x) {
    int i = blockIdx.x * blockDim.x + threadIdx.x;
    const int n4 = M_ * E_ / 4;
    if (i >= n4) return;
    float4 v = ((const float4*)x)[i];
    union { __nv_bfloat16 h[4]; uint2 u; } pk;
    pk.h[0] = __float2bfloat16(v.x);
    pk.h[1] = __float2bfloat16(v.y);
    pk.h[2] = __float2bfloat16(v.z);
    pk.h[3] = __float2bfloat16(v.w);
    ((uint2*)g_xb)[i] = pk.u;
}

// ---------------------------------------------------------------------------
// Kernel 1b: transpose+convert W [k][n] f32 -> g_wt [n][k] bf16
// ---------------------------------------------------------------------------
__global__ __launch_bounds__(256)
void convert_w_kernel(const float* __restrict__ W) {
    int i = blockIdx.x * blockDim.x + threadIdx.x;
    if (i >= GV_ * E_) return;
    int n = i >> 10;
    int k = i & 1023;
    g_wt[i] = __float2bfloat16(W[(size_t)k * GV_ + n]);
}

// ---------------------------------------------------------------------------
// Kernel 2: bf16 tensor-core GEMM  h = x @ W  (f32 accumulate)
// BM=128, BN=128, BK=32; 256 thr = 8 warps (2 x 4), warp tile 64x32.
// ---------------------------------------------------------------------------
__global__ __launch_bounds__(256, 2)
void mma_gemm_kernel() {
    __shared__ __align__(16) __nv_bfloat16 As[2][128][APITCH];
    __shared__ __align__(16) __nv_bfloat16 Bs[2][128][APITCH];

    const int tid  = threadIdx.x;
    const int lane = tid & 31;
    const int wid  = tid >> 5;
    const int bm = blockIdx.y * 128;
    const int bn = blockIdx.x * 128;
    const int wm = (wid & 1) * 64;
    const int wn = (wid >> 1) * 32;

    const int arow  = tid >> 2;
    const int acoff = (tid & 3) * 8;

    const __nv_bfloat16* ag = g_xb + (size_t)(bm + arow) * E_ + acoff;
    const __nv_bfloat16* bg = g_wt + (size_t)(bn + arow) * E_ + acoff;

    const unsigned sA = smem_u32(&As[0][0][0]);
    const unsigned sB = smem_u32(&Bs[0][0][0]);
    const unsigned dA = sA + (unsigned)(arow * APITCH + acoff) * 2u;
    const unsigned dB = sB + (unsigned)(arow * APITCH + acoff) * 2u;

    float acc[4][4][4];
    for (int i = 0; i < 4; i++)
        for (int j = 0; j < 4; j++)
            for (int k = 0; k < 4; k++)
                acc[i][j][k] = 0.0f;

    issue_tile(dA, dB, ag, bg);

    const int arow_f = wm + (lane & 15);
    const int acol_f = (lane >> 4) * 8;
    const unsigned aBase = sA + (unsigned)(arow_f * APITCH + acol_f) * 2u;
    const int brow_f = wn + (lane & 7) + ((lane >> 4) << 3);
    const int bcol_f = ((lane >> 3) & 1) * 8;
    const unsigned bBase = sB + (unsigned)(brow_f * APITCH + bcol_f) * 2u;

    for (int it = 0; it < NIT; ++it) {
        const int s = it & 1;
        if (it + 1 < NIT) {
            issue_tile(dA + (unsigned)((s ^ 1) * STG_BYTES),
                       dB + (unsigned)((s ^ 1) * STG_BYTES),
                       ag + (it + 1) * BK, bg + (it + 1) * BK);
            cp_wait1();
        } else {
            cp_wait0();
        }
        __syncthreads();

        const unsigned so = (unsigned)(s * STG_BYTES);
#pragma unroll
        for (int kk = 0; kk < 2; ++kk) {
            unsigned af[4][4];
            unsigned bf[2][4];
#pragma unroll
            for (int mi = 0; mi < 4; ++mi)
                ldsm4(af[mi], aBase + so + (unsigned)(mi * 16 * APITCH + kk * 16) * 2u);
#pragma unroll
            for (int p = 0; p < 2; ++p)
                ldsm4(bf[p], bBase + so + (unsigned)(p * 16 * APITCH + kk * 16) * 2u);
#pragma unroll
            for (int mi = 0; mi < 4; ++mi) {
#pragma unroll
                for (int p = 0; p < 2; ++p) {
                    mma16816(acc[mi][2 * p],     af[mi], bf[p][0], bf[p][1]);
                    mma16816(acc[mi][2 * p + 1], af[mi], bf[p][2], bf[p][3]);
                }
            }
        }
        __syncthreads();
    }

    const int cg = lane >> 2;
    const int tg = lane & 3;
#pragma unroll
    for (int mi = 0; mi < 4; ++mi) {
        const int row = bm + wm + mi * 16 + cg;
        float* o0 = g_h + (size_t)row * GV_ + bn + wn;
        float* o1 = o0 + 8 * GV_;
#pragma unroll
        for (int ni = 0; ni < 4; ++ni) {
            float2 v0; v0.x = acc[mi][ni][0]; v0.y = acc[mi][ni][1];
            float2 v1; v1.x = acc[mi][ni][2]; v1.y = acc[mi][ni][3];
            *(float2*)(o0 + ni * 8 + tg * 2) = v0;
            *(float2*)(o1 + ni * 8 + tg * 2) = v1;
        }
    }
}

// ---------------------------------------------------------------------------
// Kernel 3: argmax + exact rescue + histogram + gather. One warp per row.
// ---------------------------------------------------------------------------
__global__ __launch_bounds__(256)
void argmax_gather_kernel(const float* __restrict__ x,
                          const float* __restrict__ u,
                          const float* __restrict__ W,
                          const float* __restrict__ bias,
                          const float* __restrict__ codebook,
                          float* __restrict__ out) {
    const int warp = (blockIdx.x * blockDim.x + threadIdx.x) >> 5;
    const int lane = threadIdx.x & 31;
    if (warp >= ROWS_) return;

    const int r    = warp;
    const int gidx = r & 1;
    const float* hrow = g_h + (size_t)r * V_;
    const float* urow = u   + (size_t)r * V_;
    const float* brow = bias + gidx * V_;

    const float kA = 1.0f - 2.0f * 1e-7f;
    const float kB = 1e-7f;

    float vals[10];
    float best = -3.4e38f;
    int   bi   = 0;
#pragma unroll
    for (int i = 0; i < 10; i++) {
        const int v = i * 32 + lane;
        float uu = fmaf(urow[v], kA, kB);
        float gn = -logf(-logf(uu));
        float val = hrow[v] + brow[v] + gn;
        vals[i] = val;
        if (val > best) { best = val; bi = v; }
    }
#pragma unroll
    for (int off = 16; off; off >>= 1) {
        float ov = __shfl_down_sync(0xffffffffu, best, off);
        int   oi = __shfl_down_sync(0xffffffffu, bi, off);
        if (ov > best || (ov == best && oi < bi)) { best = ov; bi = oi; }
    }
    best = __shfl_sync(0xffffffffu, best, 0);
    bi   = __shfl_sync(0xffffffffu, bi, 0);

    float second = -3.4e38f;
#pragma unroll
    for (int i = 0; i < 10; i++) {
        const int v = i * 32 + lane;
        if (v != bi) second = fmaxf(second, vals[i]);
    }
#pragma unroll
    for (int off = 16; off; off >>= 1)
        second = fmaxf(second, __shfl_xor_sync(0xffffffffu, second, off));

    if (best - second < THRESH) {
        const float* xrow = x + (size_t)(r >> 1) * E_;
        float ex_best = -3.4e38f;
        int   ex_bi   = V_;
        const float cut = best - THRESH;
        for (int i = 0; i < 10; i++) {
            unsigned bal = __ballot_sync(0xffffffffu, vals[i] >= cut);
            while (bal) {
                const int j = __ffs(bal) - 1;
                bal &= bal - 1;
                const int vc = i * 32 + j;
                const int c  = gidx * V_ + vc;
                float s = 0.0f;
                for (int k = lane; k < E_; k += 32)
                    s = fmaf(xrow[k], W[(size_t)k * GV_ + c], s);
#pragma unroll
                for (int off = 16; off; off >>= 1)
                    s += __shfl_xor_sync(0xffffffffu, s, off);
                float uu = fmaf(urow[vc], kA, kB);
                float ex = s + brow[vc] + (-logf(-logf(uu)));
                if (ex > ex_best || (ex == ex_best && vc < ex_bi)) {
                    ex_best = ex;
                    ex_bi   = vc;
                }
            }
        }
        bi = ex_bi;
    }

    if (lane == 0) {
        int b = r >> 12;
        atomicAdd(&g_counts[(b * G_ + gidx) * V_ + bi], 1);
    }

    const float4* cb = (const float4*)(codebook + ((size_t)(gidx * V_ + bi)) * D_);
    float4*       op = (float4*)(out + (size_t)r * D_);
#pragma unroll
    for (int i = 0; i < 4; i++)
        op[i * 32 + lane] = cb[i * 32 + lane];
}

// ---------------------------------------------------------------------------
// Kernel 4: entropy from histograms (one warp per (b,g))
// ---------------------------------------------------------------------------
__global__ void entropy_kernel(float* __restrict__ out, int out_size) {
    const int w    = threadIdx.x >> 5;
    const int lane = threadIdx.x & 31;
    const int* c = g_counts + w * V_;

    float cv[10];
    float m = -3.4e38f;
#pragma unroll
    for (int i = 0; i < 10; i++) {
        cv[i] = (float)c[lane + i * 32];
        m = fmaxf(m, cv[i]);
    }
#pragma unroll
    for (int off = 16; off; off >>= 1)
        m = fmaxf(m, __shfl_xor_sync(0xffffffffu, m, off));

    float s = 0.0f;
#pragma unroll
    for (int i = 0; i < 10; i++)
        s += expf(cv[i] - m);
#pragma unroll
    for (int off = 16; off; off >>= 1)
        s += __shfl_xor_sync(0xffffffffu, s, off);

    float ent = 0.0f;
#pragma unroll
    for (int i = 0; i < 10; i++) {
        float p = expf(cv[i] - m) / s;
        ent += p * logf(p + 1e-8f);
    }
#pragma unroll
    for (int off = 16; off; off >>= 1)
        ent += __shfl_xor_sync(0xffffffffu, ent, off);

    __shared__ float part[32];
    if (lane == 0) part[w] = ent;
    __syncthreads();
    if (threadIdx.x == 0) {
        float t = 0.0f;
#pragma unroll
        for (int i = 0; i < 32; i++)
            t += part[i];
        out[out_size - 1] = -t / (float)(G_ * V_);
    }
}

// ---------------------------------------------------------------------------
extern "C" void kernel_launch(void* const* d_in, const int* in_sizes, int n_in,
                              void* d_out, int out_size) {
    const float* x        = (const float*)d_in[0];
    const float* u        = (const float*)d_in[1];
    const float* W        = (const float*)d_in[2];
    const float* bias     = (const float*)d_in[3];
    const float* codebook = (const float*)d_in[4];
    float* out = (float*)d_out;
    (void)in_sizes; (void)n_in;

    zero_counts_kernel<<<(B_ * G_ * V_ + 255) / 256, 256>>>();

    convert_x_kernel<<<(M_ * E_ / 4 + 255) / 256, 256>>>(x);
    convert_w_kernel<<<(GV_ * E_ + 255) / 256, 256>>>(W);

    dim3 gg(GV_ / 128, M_ / 128);
    mma_gemm_kernel<<<gg, 256>>>();

    argmax_gather_kernel<<<(ROWS_ * 32 + 255) / 256, 256>>>(x, u, W, bias, codebook, out);

    entropy_kernel<<<1, 1024>>>(out, out_size);
}

// round 6
// speedup vs baseline: 3.3365x; 1.0127x over previous
#include <cuda_runtime.h>
#include <cuda_bf16.h>
#include <math.h>

// Problem constants
#define B_  16
#define N_  2048
#define E_  1024
#define G_  2
#define V_  320
#define D_  512
#define GV_ 640
#define M_  (B_ * N_)
#define ROWS_ (M_ * G_)

#define BK   32
#define NIT  (E_ / BK)       // 32
#define APITCH 40            // bf16 elems per smem row (80B, ldsm conflict-free)
#define THRESH 0.05f

// Dynamic smem layout (bytes): 3 stages x (A 256x40 + B 128x40) bf16
#define A_STAGE_BYTES 20480  /* 256*40*2 */
#define B_STAGE_BYTES 10240  /* 128*40*2 */
#define STG_BYTES     30720  /* A+B per stage */
#define SMEM_TOTAL    92160  /* 3 * STG_BYTES */

// Device scratch (sanctioned: __device__ globals, no allocation)
__device__ __nv_bfloat16 g_xb[(size_t)M_ * E_];   // x bf16
__device__ __nv_bfloat16 g_wt[(size_t)GV_ * E_];  // W^T bf16 [n][k]
__device__ __nv_bfloat16 g_hb[(size_t)M_ * GV_];  // logits bf16 (42 MB)
__device__ int           g_counts[B_ * G_ * V_];

// ---------------------------------------------------------------------------
// PTX helpers
// ---------------------------------------------------------------------------
__device__ __forceinline__ unsigned smem_u32(const void* p) {
    unsigned a;
    asm("{ .reg .u64 t; cvta.to.shared.u64 t, %1; cvt.u32.u64 %0, t; }"
        : "=r"(a) : "l"(p));
    return a;
}

__device__ __forceinline__ void cp_async16(unsigned dst, const void* src) {
    asm volatile("cp.async.cg.shared.global [%0], [%1], 16;" :: "r"(dst), "l"(src));
}

__device__ __forceinline__ void cp_commit() {
    asm volatile("cp.async.commit_group;" ::: "memory");
}

__device__ __forceinline__ void cp_wait0() {
    asm volatile("cp.async.wait_group 0;" ::: "memory");
}

__device__ __forceinline__ void cp_wait1() {
    asm volatile("cp.async.wait_group 1;" ::: "memory");
}

__device__ __forceinline__ void ldsm4(unsigned* r, unsigned addr) {
    asm volatile("ldmatrix.sync.aligned.m8n8.x4.shared.b16 {%0,%1,%2,%3}, [%4];"
                 : "=r"(r[0]), "=r"(r[1]), "=r"(r[2]), "=r"(r[3]) : "r"(addr));
}

__device__ __forceinline__ void mma16816(float* c, const unsigned* a,
                                         unsigned b0, unsigned b1) {
    asm volatile(
        "mma.sync.aligned.m16n8k16.row.col.f32.bf16.bf16.f32 "
        "{%0,%1,%2,%3}, {%4,%5,%6,%7}, {%8,%9}, {%0,%1,%2,%3};"
        : "+f"(c[0]), "+f"(c[1]), "+f"(c[2]), "+f"(c[3])
        : "r"(a[0]), "r"(a[1]), "r"(a[2]), "r"(a[3]), "r"(b0), "r"(b1));
}

// Issue one k-tile: 2 A rows + 1 B row chunk per thread (3 x 16B)
__device__ __forceinline__ void issue_tile(unsigned dA, unsigned dB,
                                           const __nv_bfloat16* ag,
                                           const __nv_bfloat16* bg) {
    cp_async16(dA,         ag);
    cp_async16(dA + 10240, ag + (size_t)128 * E_);   // rows +128 (128*40*2 smem)
    cp_async16(dB,         bg);
    cp_commit();
}

// ---------------------------------------------------------------------------
// Kernel 0: zero histograms
// ---------------------------------------------------------------------------
__global__ void zero_counts_kernel() {
    int i = blockIdx.x * blockDim.x + threadIdx.x;
    if (i < B_ * G_ * V_) g_counts[i] = 0;
}

// ---------------------------------------------------------------------------
// Kernel 1a: convert x (f32) -> g_xb (bf16)
// ---------------------------------------------------------------------------
__global__ __launch_bounds__(256)
void convert_x_kernel(const float* __restrict__ x) {
    int i = blockIdx.x * blockDim.x + threadIdx.x;
    const int n4 = M_ * E_ / 4;
    if (i >= n4) return;
    float4 v = ((const float4*)x)[i];
    union { __nv_bfloat16 h[4]; uint2 u; } pk;
    pk.h[0] = __float2bfloat16(v.x);
    pk.h[1] = __float2bfloat16(v.y);
    pk.h[2] = __float2bfloat16(v.z);
    pk.h[3] = __float2bfloat16(v.w);
    ((uint2*)g_xb)[i] = pk.u;
}

// ---------------------------------------------------------------------------
// Kernel 1b: transpose+convert W [k][n] f32 -> g_wt [n][k] bf16
// ---------------------------------------------------------------------------
__global__ __launch_bounds__(256)
void convert_w_kernel(const float* __restrict__ W) {
    int i = blockIdx.x * blockDim.x + threadIdx.x;
    if (i >= GV_ * E_) return;
    int n = i >> 10;
    int k = i & 1023;
    g_wt[i] = __float2bfloat16(W[(size_t)k * GV_ + n]);
}

// ---------------------------------------------------------------------------
// Kernel 2: bf16 tensor-core GEMM  h = x @ W  (f32 accum, bf16 store)
// BM=256, BN=128, BK=32; 512 thr = 16 warps (4 x 4), warp tile 64x32.
// 3-stage cp.async pipeline in dynamic smem.
// ---------------------------------------------------------------------------
__global__ __launch_bounds__(512, 1)
void mma_gemm_kernel() {
    extern __shared__ __align__(16) __nv_bfloat16 smem[];

    const int tid  = threadIdx.x;
    const int lane = tid & 31;
    const int wid  = tid >> 5;           // 0..15
    const int bm = blockIdx.y * 256;
    const int bn = blockIdx.x * 128;
    const int wm = (wid & 3) * 64;       // 0,64,128,192
    const int wn = (wid >> 2) * 32;      // 0,32,64,96

    const int arow  = tid >> 2;          // 0..127
    const int acoff = (tid & 3) * 8;     // 0,8,16,24

    const __nv_bfloat16* ag = g_xb + (size_t)(bm + arow) * E_ + acoff;
    const __nv_bfloat16* bg = g_wt + (size_t)(bn + arow) * E_ + acoff;

    const unsigned sBase = smem_u32(&smem[0]);
    const unsigned dA = sBase + (unsigned)(arow * APITCH + acoff) * 2u;
    const unsigned dB = sBase + 20480u + (unsigned)(arow * APITCH + acoff) * 2u;

    float acc[4][4][4];
    for (int i = 0; i < 4; i++)
        for (int j = 0; j < 4; j++)
            for (int k = 0; k < 4; k++)
                acc[i][j][k] = 0.0f;

    // Prologue: stages 0 and 1
    issue_tile(dA, dB, ag, bg);
    issue_tile(dA + STG_BYTES, dB + STG_BYTES, ag + BK, bg + BK);

    const int arow_f = wm + (lane & 15);
    const int acol_f = (lane >> 4) * 8;
    const unsigned aBase = sBase + (unsigned)(arow_f * APITCH + acol_f) * 2u;
    const int brow_f = wn + (lane & 7) + ((lane >> 4) << 3);
    const int bcol_f = ((lane >> 3) & 1) * 8;
    const unsigned bBase = sBase + 20480u + (unsigned)(brow_f * APITCH + bcol_f) * 2u;

    for (int it = 0; it < NIT; ++it) {
        const int s = it % 3;
        if (it == NIT - 1) cp_wait0(); else cp_wait1();
        __syncthreads();

        if (it + 2 < NIT) {
            const int s2 = (it + 2) % 3;
            issue_tile(dA + (unsigned)(s2 * STG_BYTES),
                       dB + (unsigned)(s2 * STG_BYTES),
                       ag + (it + 2) * BK, bg + (it + 2) * BK);
        }

        const unsigned so = (unsigned)(s * STG_BYTES);
#pragma unroll
        for (int kk = 0; kk < 2; ++kk) {
            unsigned af[4][4];
            unsigned bf[2][4];
#pragma unroll
            for (int mi = 0; mi < 4; ++mi)
                ldsm4(af[mi], aBase + so + (unsigned)(mi * 16 * APITCH + kk * 16) * 2u);
#pragma unroll
            for (int p = 0; p < 2; ++p)
                ldsm4(bf[p], bBase + so + (unsigned)(p * 16 * APITCH + kk * 16) * 2u);
#pragma unroll
            for (int mi = 0; mi < 4; ++mi) {
#pragma unroll
                for (int p = 0; p < 2; ++p) {
                    mma16816(acc[mi][2 * p],     af[mi], bf[p][0], bf[p][1]);
                    mma16816(acc[mi][2 * p + 1], af[mi], bf[p][2], bf[p][3]);
                }
            }
        }
    }

    // Epilogue: f32 acc -> bf16x2 stores
    const int cg = lane >> 2;
    const int tg = lane & 3;
#pragma unroll
    for (int mi = 0; mi < 4; ++mi) {
        const int row = bm + wm + mi * 16 + cg;
        __nv_bfloat162* o0 =
            (__nv_bfloat162*)(g_hb + (size_t)row * GV_ + bn + wn + tg * 2);
        __nv_bfloat162* o1 =
            (__nv_bfloat162*)(g_hb + (size_t)(row + 8) * GV_ + bn + wn + tg * 2);
#pragma unroll
        for (int ni = 0; ni < 4; ++ni) {
            float2 v0; v0.x = acc[mi][ni][0]; v0.y = acc[mi][ni][1];
            float2 v1; v1.x = acc[mi][ni][2]; v1.y = acc[mi][ni][3];
            o0[ni * 4] = __float22bfloat162_rn(v0);
            o1[ni * 4] = __float22bfloat162_rn(v1);
        }
    }
}

// ---------------------------------------------------------------------------
// Kernel 3: argmax + exact rescue + histogram + gather. One warp per row.
// h is stored bf16; accept margin THRESH=0.05 covers bf16 store + mma noise.
// ---------------------------------------------------------------------------
__global__ __launch_bounds__(256)
void argmax_gather_kernel(const float* __restrict__ x,
                          const float* __restrict__ u,
                          const float* __restrict__ W,
                          const float* __restrict__ bias,
                          const float* __restrict__ codebook,
                          float* __restrict__ out) {
    const int warp = (blockIdx.x * blockDim.x + threadIdx.x) >> 5;
    const int lane = threadIdx.x & 31;
    if (warp >= ROWS_) return;

    const int r    = warp;
    const int gidx = r & 1;
    const __nv_bfloat16* hrow = g_hb + (size_t)r * V_;
    const float* urow = u + (size_t)r * V_;
    const float* brow = bias + gidx * V_;

    const float kA = 1.0f - 2.0f * 1e-7f;
    const float kB = 1e-7f;

    float vals[10];
    float best = -3.4e38f;
    int   bi   = 0;
#pragma unroll
    for (int i = 0; i < 10; i++) {
        const int v = i * 32 + lane;
        float uu = fmaf(urow[v], kA, kB);
        float gn = -logf(-logf(uu));
        float val = __bfloat162float(hrow[v]) + brow[v] + gn;
        vals[i] = val;
        if (val > best) { best = val; bi = v; }
    }
#pragma unroll
    for (int off = 16; off; off >>= 1) {
        float ov = __shfl_down_sync(0xffffffffu, best, off);
        int   oi = __shfl_down_sync(0xffffffffu, bi, off);
        if (ov > best || (ov == best && oi < bi)) { best = ov; bi = oi; }
    }
    best = __shfl_sync(0xffffffffu, best, 0);
    bi   = __shfl_sync(0xffffffffu, bi, 0);

    float second = -3.4e38f;
#pragma unroll
    for (int i = 0; i < 10; i++) {
        const int v = i * 32 + lane;
        if (v != bi) second = fmaxf(second, vals[i]);
    }
#pragma unroll
    for (int off = 16; off; off >>= 1)
        second = fmaxf(second, __shfl_xor_sync(0xffffffffu, second, off));

    if (best - second < THRESH) {
        const float* xrow = x + (size_t)(r >> 1) * E_;
        float ex_best = -3.4e38f;
        int   ex_bi   = V_;
        const float cut = best - THRESH;
        for (int i = 0; i < 10; i++) {
            unsigned bal = __ballot_sync(0xffffffffu, vals[i] >= cut);
            while (bal) {
                const int j = __ffs(bal) - 1;
                bal &= bal - 1;
                const int vc = i * 32 + j;
                const int c  = gidx * V_ + vc;
                float s = 0.0f;
                for (int k = lane; k < E_; k += 32)
                    s = fmaf(xrow[k], W[(size_t)k * GV_ + c], s);
#pragma unroll
                for (int off = 16; off; off >>= 1)
                    s += __shfl_xor_sync(0xffffffffu, s, off);
                float uu = fmaf(urow[vc], kA, kB);
                float ex = s + brow[vc] + (-logf(-logf(uu)));
                if (ex > ex_best || (ex == ex_best && vc < ex_bi)) {
                    ex_best = ex;
                    ex_bi   = vc;
                }
            }
        }
        bi = ex_bi;
    }

    if (lane == 0) {
        int b = r >> 12;
        atomicAdd(&g_counts[(b * G_ + gidx) * V_ + bi], 1);
    }

    const float4* cb = (const float4*)(codebook + ((size_t)(gidx * V_ + bi)) * D_);
    float4*       op = (float4*)(out + (size_t)r * D_);
#pragma unroll
    for (int i = 0; i < 4; i++)
        op[i * 32 + lane] = cb[i * 32 + lane];
}

// ---------------------------------------------------------------------------
// Kernel 4: entropy from histograms (one warp per (b,g))
// ---------------------------------------------------------------------------
__global__ void entropy_kernel(float* __restrict__ out, int out_size) {
    const int w    = threadIdx.x >> 5;
    const int lane = threadIdx.x & 31;
    const int* c = g_counts + w * V_;

    float cv[10];
    float m = -3.4e38f;
#pragma unroll
    for (int i = 0; i < 10; i++) {
        cv[i] = (float)c[lane + i * 32];
        m = fmaxf(m, cv[i]);
    }
#pragma unroll
    for (int off = 16; off; off >>= 1)
        m = fmaxf(m, __shfl_xor_sync(0xffffffffu, m, off));

    float s = 0.0f;
#pragma unroll
    for (int i = 0; i < 10; i++)
        s += expf(cv[i] - m);
#pragma unroll
    for (int off = 16; off; off >>= 1)
        s += __shfl_xor_sync(0xffffffffu, s, off);

    float ent = 0.0f;
#pragma unroll
    for (int i = 0; i < 10; i++) {
        float p = expf(cv[i] - m) / s;
        ent += p * logf(p + 1e-8f);
    }
#pragma unroll
    for (int off = 16; off; off >>= 1)
        ent += __shfl_xor_sync(0xffffffffu, ent, off);

    __shared__ float part[32];
    if (lane == 0) part[w] = ent;
    __syncthreads();
    if (threadIdx.x == 0) {
        float t = 0.0f;
#pragma unroll
        for (int i = 0; i < 32; i++)
            t += part[i];
        out[out_size - 1] = -t / (float)(G_ * V_);
    }
}

// ---------------------------------------------------------------------------
extern "C" void kernel_launch(void* const* d_in, const int* in_sizes, int n_in,
                              void* d_out, int out_size) {
    const float* x        = (const float*)d_in[0];
    const float* u        = (const float*)d_in[1];
    const float* W        = (const float*)d_in[2];
    const float* bias     = (const float*)d_in[3];
    const float* codebook = (const float*)d_in[4];
    float* out = (float*)d_out;
    (void)in_sizes; (void)n_in;

    // Opt-in >48KB dynamic smem (immediate API call, not a graph node)
    cudaFuncSetAttribute(mma_gemm_kernel,
                         cudaFuncAttributeMaxDynamicSharedMemorySize, SMEM_TOTAL);

    zero_counts_kernel<<<(B_ * G_ * V_ + 255) / 256, 256>>>();

    convert_x_kernel<<<(M_ * E_ / 4 + 255) / 256, 256>>>(x);
    convert_w_kernel<<<(GV_ * E_ + 255) / 256, 256>>>(W);

    dim3 gg(GV_ / 128, M_ / 256);   // (5, 128)
    mma_gemm_kernel<<<gg, 512, SMEM_TOTAL>>>();

    argmax_gather_kernel<<<(ROWS_ * 32 + 255) / 256, 256>>>(x, u, W, bias, codebook, out);

    entropy_kernel<<<1, 1024>>>(out, out_size);
}